// round 1
// baseline (speedup 1.0000x reference)
#include <cuda_runtime.h>
#include <math.h>

#define NV 24576
#define NC 98304
#define NE 294912
#define NL 49152              // 2*NV
#define INV_M (1.0f/12582912.0f)   // 1/(NC*128)

// ---------------- workspace layout (floats) ----------------
static constexpr size_t O_VARS   = 0;
static constexpr size_t O_CLS    = O_VARS  + (size_t)NV*128;
static constexpr size_t O_XV     = O_CLS   + (size_t)NC*128;
static constexpr size_t O_XC     = O_XV    + (size_t)NV*132;
static constexpr size_t O_HV     = O_XC    + (size_t)NC*132;   // NV x 256
static constexpr size_t O_HV2    = O_HV    + (size_t)NV*256;   // NV x 256
static constexpr size_t O_VQ     = O_HV2   + (size_t)NV*256;
static constexpr size_t O_HC     = O_VQ    + (size_t)NV*128;   // NC x 256
static constexpr size_t O_CQ     = O_HC    + (size_t)NC*256;
static constexpr size_t O_CSUM   = O_CQ    + (size_t)NC*128;
static constexpr size_t O_LOSS   = O_CSUM  + (size_t)NC*128;
static constexpr size_t O_CMIN   = O_LOSS  + (size_t)NC*128;   // NC x 384
static constexpr size_t O_CDATA  = O_CMIN  + (size_t)NC*384;   // NC x 256
static constexpr size_t O_DLITS  = O_CDATA + (size_t)NC*256;   // NL x 128
static constexpr size_t O_VL     = O_DLITS + (size_t)NL*128;   // NL x 128
static constexpr size_t O_UNIT   = O_VL    + (size_t)NL*128;   // NV x 512
static constexpr size_t O_VOUT   = O_UNIT  + (size_t)NV*512;
static constexpr size_t O_DEGW   = O_VOUT  + (size_t)NV*128;   // NL
static constexpr size_t O_VDEGW  = O_DEGW  + NL;               // NV
static constexpr size_t O_STAT   = O_VDEGW + NV;               // 128 sum, 128 ssq, 1 scale
static constexpr size_t WS_TOTAL = O_STAT  + 260;

__device__ float g_ws[WS_TOTAL];
__device__ int   g_deg[NL];

// ---------------- small helpers ----------------
__device__ __forceinline__ float sigm(float x){ return 1.f/(1.f+expf(-x)); }
__device__ __forceinline__ float softplusf(float x){ return fmaxf(x,0.f)+log1pf(expf(-fabsf(x))); }

__global__ void k_zero(float* p, size_t n){
    size_t i = (size_t)blockIdx.x*blockDim.x + threadIdx.x;
    if (i < n) p[i] = 0.f;
}
__global__ void k_fill1(float* p, size_t n){
    size_t i = (size_t)blockIdx.x*blockDim.x + threadIdx.x;
    if (i < n) p[i] = 1.f;
}
__global__ void k_zero_int(int* p, int n){
    int i = blockIdx.x*blockDim.x + threadIdx.x;
    if (i < n) p[i] = 0;
}
__global__ void k_count(const int* __restrict__ lit){
    int e = blockIdx.x*blockDim.x + threadIdx.x;
    if (e < NE) atomicAdd(&g_deg[lit[e]], 1);
}
__global__ void k_weights(){
    int l = blockIdx.x*blockDim.x + threadIdx.x;
    if (l < NL) g_ws[O_DEGW + l] = rsqrtf(fmaxf((float)g_deg[l], 1.f));
    if (l < NV) g_ws[O_VDEGW + l] = 4.f*rsqrtf(fmaxf((float)(g_deg[l] + g_deg[l+NV]), 1.f));
}

// concat [n,128] with [n,4] noise -> [n,132]
__global__ void k_concat(const float* __restrict__ a, const float* __restrict__ nz,
                         float* __restrict__ x, int n){
    size_t i = (size_t)blockIdx.x*blockDim.x + threadIdx.x;
    if (i >= (size_t)n*132) return;
    int r = (int)(i/132), c = (int)(i%132);
    x[i] = (c < 128) ? a[(size_t)r*128 + c] : nz[(size_t)r*4 + (c-128)];
}

// ---------------- SGEMM: C[M,N] = act(A[M,K] @ W[K,N] + bias) ----------------
// BM=BN=128, BK=8, 256 threads, 8x8 per thread. M,N multiples of 128, K arbitrary.
__global__ void __launch_bounds__(256)
k_gemm(const float* __restrict__ A, const float* __restrict__ W,
       const float* __restrict__ bias, float* __restrict__ C,
       int M, int K, int N, int do_relu)
{
    __shared__ float As[8][132];
    __shared__ float Bs[8][128];
    const int tid = threadIdx.x;
    const int bm = blockIdx.y * 128;
    const int bn = blockIdx.x * 128;
    const int tx = tid & 15, ty = tid >> 4;
    float acc[8][8] = {{0.f}};

    const int lr = tid >> 3;          // 0..31
    const int lc = tid & 7;           // 0..7
    const int brow = tid >> 5;        // 0..7
    const int bcol = (tid & 31) * 4;  // 0..124

    for (int k0 = 0; k0 < K; k0 += 8) {
        #pragma unroll
        for (int i = 0; i < 4; i++) {
            int row = lr + 32*i;
            int k = k0 + lc;
            As[lc][row] = (k < K) ? A[(size_t)(bm+row)*K + k] : 0.f;
        }
        {
            int k = k0 + brow;
            float4 v = make_float4(0.f,0.f,0.f,0.f);
            if (k < K) v = *reinterpret_cast<const float4*>(&W[(size_t)k*N + bn + bcol]);
            *reinterpret_cast<float4*>(&Bs[brow][bcol]) = v;
        }
        __syncthreads();
        #pragma unroll
        for (int kk = 0; kk < 8; kk++) {
            float af[8], bf[8];
            #pragma unroll
            for (int i = 0; i < 8; i++) af[i] = As[kk][ty*8 + i];
            #pragma unroll
            for (int j = 0; j < 8; j++) bf[j] = Bs[kk][tx*8 + j];
            #pragma unroll
            for (int i = 0; i < 8; i++)
                #pragma unroll
                for (int j = 0; j < 8; j++)
                    acc[i][j] = fmaf(af[i], bf[j], acc[i][j]);
        }
        __syncthreads();
    }
    #pragma unroll
    for (int i = 0; i < 8; i++) {
        int row = bm + ty*8 + i;
        #pragma unroll
        for (int j = 0; j < 8; j += 4) {
            float4 o;
            float* po = &o.x;
            #pragma unroll
            for (int q = 0; q < 4; q++) {
                int col = bn + tx*8 + j + q;
                float v = acc[i][j+q] + bias[col];
                po[q] = do_relu ? fmaxf(v, 0.f) : v;
            }
            *reinterpret_cast<float4*>(&C[(size_t)row*N + bn + tx*8 + j]) = o;
        }
    }
}

// ---------------- edge scatters ----------------
// csum[clause] += softplus(lit-signed vq)
__global__ void k_csum(const int* __restrict__ lit, const int* __restrict__ cls){
    int e = blockIdx.x, f = threadIdx.x;
    int l = lit[e];
    float z = (l < NV) ? g_ws[O_VQ + (size_t)l*128 + f]
                       : -g_ws[O_VQ + (size_t)(l-NV)*128 + f];
    atomicAdd(&g_ws[O_CSUM + (size_t)cls[e]*128 + f], softplusf(z));
}

// dst[sidx[e]] += src[gidx[e]] (src row stride given; dst stride 128)
__global__ void k_scatter(const float* __restrict__ src, int sstride,
                          const int* __restrict__ gidx, const int* __restrict__ sidx,
                          float* __restrict__ dst){
    int e = blockIdx.x, f = threadIdx.x;
    atomicAdd(&dst[(size_t)sidx[e]*128 + f], src[(size_t)gidx[e]*sstride + f]);
}

// loss, cgrad, and cm-input build (fused)
__global__ void k_loss(){
    size_t i = (size_t)blockIdx.x*blockDim.x + threadIdx.x;
    if (i >= (size_t)NC*128) return;
    int c = (int)(i >> 7), f = (int)(i & 127);
    float s = sigm(g_ws[O_CQ + i]);
    float l = expf(-g_ws[O_CSUM + i]) * s;
    g_ws[O_LOSS + i] = l;
    size_t b = (size_t)c*384;
    g_ws[O_CMIN + b + f]       = g_ws[O_CLS + i];
    g_ws[O_CMIN + b + 128 + f] = 4.f * l;
    g_ws[O_CMIN + b + 256 + f] = l * (1.f - s) * INV_M;
}

// unit = [vgrad | variables | vl_pos*dw | vl_neg*dw]
__global__ void k_unit(){
    int v = blockIdx.x, f = threadIdx.x;
    size_t i = (size_t)v*128 + f;
    float vq = g_ws[O_VQ + i];
    float sp = sigm(vq);
    float sn = 1.f - sp;
    float g = -INV_M * (g_ws[O_DLITS + i]*sp - g_ws[O_DLITS + (size_t)NV*128 + i]*sn)
              * g_ws[O_VDEGW + v];
    size_t b = (size_t)v*512;
    g_ws[O_UNIT + b + f]        = g;
    g_ws[O_UNIT + b + 128 + f]  = g_ws[O_VARS + i];
    g_ws[O_UNIT + b + 256 + f]  = g_ws[O_VL + i] * g_ws[O_DEGW + v];
    g_ws[O_UNIT + b + 384 + f]  = g_ws[O_VL + (size_t)NV*128 + i] * g_ws[O_DEGW + NV + v];
}

// ---------------- pair_norm ----------------
__global__ void k_pn_stats(const float* __restrict__ x, int stride, int off, int n){
    int f = threadIdx.x;
    float s = 0.f, q = 0.f;
    for (int r = blockIdx.x; r < n; r += gridDim.x) {
        float v = x[(size_t)r*stride + off + f];
        s += v; q += v*v;
    }
    atomicAdd(&g_ws[O_STAT + f], s);
    atomicAdd(&g_ws[O_STAT + 128 + f], q);
}
__global__ void k_pn_scale(float n){
    int f = threadIdx.x;
    float mean = g_ws[O_STAT + f] / n;
    float var  = g_ws[O_STAT + 128 + f] / n - mean*mean;
    __shared__ float sh[128];
    sh[f] = var; __syncthreads();
    for (int s = 64; s > 0; s >>= 1) { if (f < s) sh[f] += sh[f+s]; __syncthreads(); }
    g_ws[O_STAT + f] = mean;
    if (f == 0) g_ws[O_STAT + 256] = rsqrtf(sh[0]*(1.f/128.f) + 1e-6f);
}
__global__ void k_pn_apply(const float* __restrict__ x, int stride, int off,
                           float* __restrict__ dst){
    int r = blockIdx.x, f = threadIdx.x;
    float scale = g_ws[O_STAT + 256];
    float v = (x[(size_t)r*stride + off + f] - g_ws[O_STAT + f]) * scale;
    size_t i = (size_t)r*128 + f;
    dst[i] = v*0.25f + 0.1f*dst[i];
}

// ---------------- output head: per-row dot + sigmoid/softplus ----------------
__global__ void k_logits(const float* __restrict__ H, const float* __restrict__ w1,
                         const float* __restrict__ b1, float* __restrict__ out, int round){
    __shared__ float wv[128];
    int t = threadIdx.x;
    wv[t] = w1[t];
    __syncthreads();
    int warp = t >> 5, lane = t & 31;
    int row = blockIdx.x*4 + warp;
    float s = 0.f;
    #pragma unroll
    for (int i = lane; i < 128; i += 32) s += H[(size_t)row*128 + i] * wv[i];
    #pragma unroll
    for (int o = 16; o > 0; o >>= 1) s += __shfl_xor_sync(0xffffffffu, s, o);
    if (lane == 0) {
        float x = s + b1[0];
        out[(size_t)round*NC + row] = sigm(x);
        out[(size_t)4*NC + (size_t)round*NC + row] = softplusf(x);
    }
}

// ---------------- host ----------------
static void gemm(const float* A, const float* W, const float* b, float* C,
                 int M, int K, int N, int relu){
    dim3 grid(N/128, M/128);
    k_gemm<<<grid, 256>>>(A, W, b, C, M, K, N, relu);
}

extern "C" void kernel_launch(void* const* d_in, const int* in_sizes, int n_in,
                              void* d_out, int out_size)
{
    const int*   edge_lit    = (const int*)d_in[0];
    const int*   edge_clause = (const int*)d_in[1];
    const float* noise_v = (const float*)d_in[2];
    const float* noise_c = (const float*)d_in[3];
    const float* vq_w0 = (const float*)d_in[4];  const float* vq_b0 = (const float*)d_in[5];
    const float* vq_w1 = (const float*)d_in[6];  const float* vq_b1 = (const float*)d_in[7];
    const float* cq_w0 = (const float*)d_in[8];  const float* cq_b0 = (const float*)d_in[9];
    const float* cq_w1 = (const float*)d_in[10]; const float* cq_b1 = (const float*)d_in[11];
    const float* cm_w0 = (const float*)d_in[12]; const float* cm_b0 = (const float*)d_in[13];
    const float* cm_w1 = (const float*)d_in[14]; const float* cm_b1 = (const float*)d_in[15];
    const float* ug_w0 = (const float*)d_in[16]; const float* ug_b0 = (const float*)d_in[17];
    const float* ug_w1 = (const float*)d_in[18]; const float* ug_b1 = (const float*)d_in[19];
    const float* ug_w2 = (const float*)d_in[20]; const float* ug_b2 = (const float*)d_in[21];
    const float* co_w0 = (const float*)d_in[22]; const float* co_b0 = (const float*)d_in[23];
    const float* co_w1 = (const float*)d_in[24]; const float* co_b1 = (const float*)d_in[25];
    float* out = (float*)d_out;

    float* ws; cudaGetSymbolAddress((void**)&ws, g_ws);
    int* deg;  cudaGetSymbolAddress((void**)&deg, g_deg);

    // ---- setup ----
    k_zero_int<<<(NL+255)/256, 256>>>(deg, NL);
    k_count<<<(NE+255)/256, 256>>>(edge_lit);
    k_weights<<<(NL+255)/256, 256>>>();
    {
        size_t n = (size_t)NV*128;
        k_fill1<<<(unsigned)((n+255)/256), 256>>>(ws + O_VARS, n);
        n = (size_t)NC*128;
        k_fill1<<<(unsigned)((n+255)/256), 256>>>(ws + O_CLS, n);
    }

    for (int r = 0; r < 4; r++) {
        const float* nv_r = noise_v + (size_t)r*NV*4;
        const float* nc_r = noise_c + (size_t)r*NC*4;

        // inputs to vq/cq MLPs
        k_concat<<<(unsigned)(((size_t)NV*132 + 255)/256), 256>>>(ws+O_VARS, nv_r, ws+O_XV, NV);
        k_concat<<<(unsigned)(((size_t)NC*132 + 255)/256), 256>>>(ws+O_CLS,  nc_r, ws+O_XC, NC);

        gemm(ws+O_XV, vq_w0, vq_b0, ws+O_HV, NV, 132, 128, 1);
        gemm(ws+O_HV, vq_w1, vq_b1, ws+O_VQ, NV, 128, 128, 0);
        gemm(ws+O_XC, cq_w0, cq_b0, ws+O_HC, NC, 132, 128, 1);
        gemm(ws+O_HC, cq_w1, cq_b1, ws+O_CQ, NC, 128, 128, 0);

        // csum = segsum(softplus(lits)[edge_lit] by edge_clause)
        {
            size_t n = (size_t)NC*128;
            k_zero<<<(unsigned)((n+255)/256), 256>>>(ws+O_CSUM, n);
        }
        k_csum<<<NE, 128>>>(edge_lit, edge_clause);

        // loss / cgrad / cm-input
        k_loss<<<(unsigned)(((size_t)NC*128 + 255)/256), 256>>>();

        // dlits = segsum(loss[edge_clause] by edge_lit)
        {
            size_t n = (size_t)NL*128;
            k_zero<<<(unsigned)((n+255)/256), 256>>>(ws+O_DLITS, n);
        }
        k_scatter<<<NE, 128>>>(ws+O_LOSS, 128, edge_clause, edge_lit, ws+O_DLITS);

        // clause message MLP
        gemm(ws+O_CMIN, cm_w0, cm_b0, ws+O_HC,    NC, 384, 256, 1);
        gemm(ws+O_HC,   cm_w1, cm_b1, ws+O_CDATA, NC, 256, 256, 0);

        // variables_loss = segsum(cdata[:, :128][edge_clause] by edge_lit)
        {
            size_t n = (size_t)NL*128;
            k_zero<<<(unsigned)((n+255)/256), 256>>>(ws+O_VL, n);
        }
        k_scatter<<<NE, 128>>>(ws+O_CDATA, 256, edge_clause, edge_lit, ws+O_VL);

        // clauses = pair_norm(cdata[:,128:])*0.25 + 0.1*clauses
        k_zero<<<2, 256>>>(ws+O_STAT, 257);
        k_pn_stats<<<512, 128>>>(ws+O_CDATA, 256, 128, NC);
        k_pn_scale<<<1, 128>>>((float)NC);
        k_pn_apply<<<NC, 128>>>(ws+O_CDATA, 256, 128, ws+O_CLS);

        // unit + variable update MLP3
        k_unit<<<NV, 128>>>();
        gemm(ws+O_UNIT, ug_w0, ug_b0, ws+O_HV,   NV, 512, 256, 1);
        gemm(ws+O_HV,   ug_w1, ug_b1, ws+O_HV2,  NV, 256, 256, 1);
        gemm(ws+O_HV2,  ug_w2, ug_b2, ws+O_VOUT, NV, 256, 128, 0);

        k_zero<<<2, 256>>>(ws+O_STAT, 257);
        k_pn_stats<<<512, 128>>>(ws+O_VOUT, 128, 0, NV);
        k_pn_scale<<<1, 128>>>((float)NV);
        k_pn_apply<<<NV, 128>>>(ws+O_VOUT, 128, 0, ws+O_VARS);

        // output head on updated clauses
        gemm(ws+O_CLS, co_w0, co_b0, ws+O_HC, NC, 128, 128, 1);
        k_logits<<<NC/4, 128>>>(ws+O_HC, co_w1, co_b1, out, r);
    }
}

// round 3
// speedup vs baseline: 1.6720x; 1.6720x over previous
#include <cuda_runtime.h>
#include <cuda_bf16.h>
#include <math.h>
#include <stdint.h>

#define NV 24576
#define NC 98304
#define NE 294912
#define NL 49152              // 2*NV
#define INV_M (1.0f/12582912.0f)   // 1/(NC*128)

// ---------------- workspace layout (floats) ----------------
static constexpr size_t O_VARS   = 0;
static constexpr size_t O_CLS    = O_VARS  + (size_t)NV*128;
static constexpr size_t O_XV     = O_CLS   + (size_t)NC*128;
static constexpr size_t O_XC     = O_XV    + (size_t)NV*132;
static constexpr size_t O_HV     = O_XC    + (size_t)NC*132;   // NV x 256
static constexpr size_t O_HV2    = O_HV    + (size_t)NV*256;   // NV x 256
static constexpr size_t O_VQ     = O_HV2   + (size_t)NV*256;
static constexpr size_t O_HC     = O_VQ    + (size_t)NV*128;   // NC x 256
static constexpr size_t O_CQ     = O_HC    + (size_t)NC*256;
static constexpr size_t O_CSUM   = O_CQ    + (size_t)NC*128;
static constexpr size_t O_LOSS   = O_CSUM  + (size_t)NC*128;
static constexpr size_t O_CMIN   = O_LOSS  + (size_t)NC*128;   // NC x 384
static constexpr size_t O_CDATA  = O_CMIN  + (size_t)NC*384;   // NC x 256
static constexpr size_t O_DLITS  = O_CDATA + (size_t)NC*256;   // NL x 128
static constexpr size_t O_VL     = O_DLITS + (size_t)NL*128;   // NL x 128
static constexpr size_t O_UNIT   = O_VL    + (size_t)NL*128;   // NV x 512
static constexpr size_t O_VOUT   = O_UNIT  + (size_t)NV*512;
static constexpr size_t O_DEGW   = O_VOUT  + (size_t)NV*128;   // NL
static constexpr size_t O_VDEGW  = O_DEGW  + NL;               // NV
static constexpr size_t O_STAT   = O_VDEGW + NV;               // 128 sum, 128 ssq, 1 scale
static constexpr size_t O_WT     = O_STAT  + 260;              // bf16 split weights
static constexpr size_t WS_TOTAL = O_WT + 480000;

// weight offsets in HALVES within each of the hi/lo bf16 arrays ([N][KP] row-major)
static constexpr size_t WH_TOTAL = 477184;
static constexpr size_t OW_vq0 = 0;       // N=128, K=132, KP=136
static constexpr size_t OW_vq1 = 17408;   // 128,128,128
static constexpr size_t OW_cq0 = 33792;   // 128,132,136
static constexpr size_t OW_cq1 = 51200;   // 128,128,128
static constexpr size_t OW_cm0 = 67584;   // 256,384,384
static constexpr size_t OW_cm1 = 165888;  // 256,256,256
static constexpr size_t OW_ug0 = 231424;  // 256,512,512
static constexpr size_t OW_ug1 = 362496;  // 256,256,256
static constexpr size_t OW_ug2 = 428032;  // 128,256,256
static constexpr size_t OW_co0 = 460800;  // 128,128,128

__device__ float g_ws[WS_TOTAL];
__device__ int   g_deg[NL];

// ---------------- PTX helpers ----------------
__device__ __forceinline__ uint32_t smem_u32(const void* p){
    uint32_t a;
    asm("{ .reg .u64 t; cvta.to.shared.u64 t, %1; cvt.u32.u64 %0, t; }" : "=r"(a) : "l"(p));
    return a;
}
__device__ __forceinline__ void ldsm4(uint32_t* r, uint32_t addr){
    asm volatile("ldmatrix.sync.aligned.m8n8.x4.shared.b16 {%0,%1,%2,%3}, [%4];"
        : "=r"(r[0]), "=r"(r[1]), "=r"(r[2]), "=r"(r[3]) : "r"(addr));
}
__device__ __forceinline__ void mma_bf16(float* c, const uint32_t* a, const uint32_t* b){
    asm volatile("mma.sync.aligned.m16n8k16.row.col.f32.bf16.bf16.f32 "
        "{%0,%1,%2,%3}, {%4,%5,%6,%7}, {%8,%9}, {%0,%1,%2,%3};"
        : "+f"(c[0]), "+f"(c[1]), "+f"(c[2]), "+f"(c[3])
        : "r"(a[0]), "r"(a[1]), "r"(a[2]), "r"(a[3]), "r"(b[0]), "r"(b[1]));
}
__device__ __forceinline__ uint32_t pack_bf16x2(float lo, float hi){
    uint32_t r;
    asm("cvt.rn.bf16x2.f32 %0, %1, %2;" : "=r"(r) : "f"(hi), "f"(lo));
    return r;
}

// ---------------- bf16-split MMA GEMM ----------------
// C[M,Ntot] (this block: rows bm..bm+127, cols bn..bn+127)
//   = act(A[M,K](fp32) @ W + bias), W presplit to Bh/Bl bf16 [Ntot][KP] row-major.
__global__ void __launch_bounds__(256, 1)
k_mma(const float* __restrict__ A, const __nv_bfloat16* __restrict__ Bhg,
      const __nv_bfloat16* __restrict__ Blg, const float* __restrict__ bias,
      float* __restrict__ C, int K, int KP, int Ntot, int relu)
{
    extern __shared__ __align__(16) char smem[];
    const uint32_t sbase = smem_u32(smem);
    const int t = threadIdx.x;
    const int lane = t & 31, wid = t >> 5;
    const int warp_m = wid & 1, warp_n = wid >> 1;
    const int bm = blockIdx.y * 128;
    const int bn = blockIdx.x * 128;

    constexpr int LDH = 40;               // halves per row (32 data + 8 pad)
    constexpr int AH_OFF = 0;
    constexpr int AL_OFF = 128*LDH;
    constexpr int BH_OFF = 2*128*LDH;
    constexpr int BL_OFF = 3*128*LDH;
    constexpr int STAGE_B = 4*128*LDH*2;  // bytes per stage = 40960

    float acc[4][4][4];
    #pragma unroll
    for (int i=0;i<4;i++)
        #pragma unroll
        for(int j=0;j<4;j++)
            #pragma unroll
            for(int q=0;q<4;q++) acc[i][j][q]=0.f;

    const int nch = (K + 31) >> 5;
    float4 aReg[4];
    uint4  bhReg[2], blReg[2];

    auto loadA = [&](int c){
        const int k0 = c << 5;
        #pragma unroll
        for (int i = 0; i < 4; i++) {
            int idx = t + i*256;
            int row = idx >> 3, col4 = (idx & 7) << 2;
            int gk = k0 + col4;
            aReg[i] = (gk < K) ? *reinterpret_cast<const float4*>(&A[(size_t)(bm+row)*K + gk])
                               : make_float4(0.f,0.f,0.f,0.f);
        }
    };
    auto loadB = [&](int c){
        const int k0 = c << 5;
        #pragma unroll
        for (int i = 0; i < 2; i++) {
            int idx = t + i*256;
            int row = idx >> 2, q = idx & 3;
            int gk = k0 + q*8;
            if (gk + 8 <= KP) {   // KP multiple of 8; pad region is zero-filled
                size_t off = (size_t)(bn+row)*KP + gk;
                bhReg[i] = *reinterpret_cast<const uint4*>(&Bhg[off]);
                blReg[i] = *reinterpret_cast<const uint4*>(&Blg[off]);
            } else {
                bhReg[i] = make_uint4(0,0,0,0);
                blReg[i] = make_uint4(0,0,0,0);
            }
        }
    };
    auto storeStage = [&](int buf){
        char* sc = smem + buf*STAGE_B;
        #pragma unroll
        for (int i = 0; i < 4; i++) {
            int idx = t + i*256;
            int row = idx >> 3, col4 = (idx & 7) << 2;
            uint32_t h0 = pack_bf16x2(aReg[i].x, aReg[i].y);
            uint32_t h1 = pack_bf16x2(aReg[i].z, aReg[i].w);
            float hx = __uint_as_float(h0 << 16);
            float hy = __uint_as_float(h0 & 0xffff0000u);
            float hz = __uint_as_float(h1 << 16);
            float hw = __uint_as_float(h1 & 0xffff0000u);
            uint32_t l0 = pack_bf16x2(aReg[i].x - hx, aReg[i].y - hy);
            uint32_t l1 = pack_bf16x2(aReg[i].z - hz, aReg[i].w - hw);
            int boff = (row*LDH + col4)*2;
            *reinterpret_cast<uint2*>(sc + AH_OFF*2 + boff) = make_uint2(h0,h1);
            *reinterpret_cast<uint2*>(sc + AL_OFF*2 + boff) = make_uint2(l0,l1);
        }
        #pragma unroll
        for (int i = 0; i < 2; i++) {
            int idx = t + i*256;
            int row = idx >> 2, q = idx & 3;
            int boff = (row*LDH + q*8)*2;
            *reinterpret_cast<uint4*>(sc + BH_OFF*2 + boff) = bhReg[i];
            *reinterpret_cast<uint4*>(sc + BL_OFF*2 + boff) = blReg[i];
        }
    };
    auto compute = [&](int buf){
        const uint32_t sb = sbase + buf*STAGE_B;
        const int grp = lane >> 3, r = lane & 7;
        #pragma unroll
        for (int ks = 0; ks < 32; ks += 16) {
            uint32_t aH[4][4], aL[4][4], bH[4][2], bL[4][2];
            #pragma unroll
            for (int mt = 0; mt < 4; mt++) {
                int arow = warp_m*64 + mt*16 + (grp & 1)*8 + r;
                int acol = ks + (grp >> 1)*8;
                uint32_t adr = sb + (uint32_t)(arow*LDH + acol)*2;
                ldsm4(aH[mt], adr + AH_OFF*2);
                ldsm4(aL[mt], adr + AL_OFF*2);
            }
            #pragma unroll
            for (int p = 0; p < 2; p++) {
                int brow = warp_n*32 + p*16 + (grp >> 1)*8 + r;
                int bcol = ks + (grp & 1)*8;
                uint32_t adr = sb + (uint32_t)(brow*LDH + bcol)*2;
                uint32_t tmp[4];
                ldsm4(tmp, adr + BH_OFF*2);
                bH[2*p][0]=tmp[0]; bH[2*p][1]=tmp[1]; bH[2*p+1][0]=tmp[2]; bH[2*p+1][1]=tmp[3];
                ldsm4(tmp, adr + BL_OFF*2);
                bL[2*p][0]=tmp[0]; bL[2*p][1]=tmp[1]; bL[2*p+1][0]=tmp[2]; bL[2*p+1][1]=tmp[3];
            }
            #pragma unroll
            for (int mt = 0; mt < 4; mt++)
                #pragma unroll
                for (int nt = 0; nt < 4; nt++) {
                    mma_bf16(acc[mt][nt], aH[mt], bH[nt]);
                    mma_bf16(acc[mt][nt], aH[mt], bL[nt]);
                    mma_bf16(acc[mt][nt], aL[mt], bH[nt]);
                }
        }
    };

    loadA(0); loadB(0);
    storeStage(0);
    __syncthreads();
    for (int c = 0; c < nch; c++) {
        if (c+1 < nch) { loadA(c+1); loadB(c+1); }
        compute(c & 1);
        __syncthreads();
        if (c+1 < nch) { storeStage((c+1)&1); __syncthreads(); }
    }

    // epilogue
    #pragma unroll
    for (int mt = 0; mt < 4; mt++) {
        int row0 = bm + warp_m*64 + mt*16 + (lane >> 2);
        #pragma unroll
        for (int nt = 0; nt < 4; nt++) {
            int col = bn + warp_n*32 + nt*8 + (lane & 3)*2;
            float2 bv = *reinterpret_cast<const float2*>(&bias[col]);
            float v0 = acc[mt][nt][0] + bv.x, v1 = acc[mt][nt][1] + bv.y;
            float v2 = acc[mt][nt][2] + bv.x, v3 = acc[mt][nt][3] + bv.y;
            if (relu) { v0=fmaxf(v0,0.f); v1=fmaxf(v1,0.f); v2=fmaxf(v2,0.f); v3=fmaxf(v3,0.f); }
            *reinterpret_cast<float2*>(&C[(size_t)row0*Ntot + col])     = make_float2(v0,v1);
            *reinterpret_cast<float2*>(&C[(size_t)(row0+8)*Ntot + col]) = make_float2(v2,v3);
        }
    }
}

// weight transpose + bf16 split: W[K,N] -> hi/lo [N,KP] bf16 (pad zero-filled)
__global__ void k_wsplit(const float* __restrict__ W, __nv_bfloat16* __restrict__ hi,
                         __nv_bfloat16* __restrict__ lo, int K, int N, int KP){
    int idx = blockIdx.x*blockDim.x + threadIdx.x;
    if (idx >= N*KP) return;
    int n = idx / KP, k = idx % KP;
    float v = (k < K) ? W[(size_t)k*N + n] : 0.f;
    __nv_bfloat16 h = __float2bfloat16(v);
    hi[idx] = h;
    lo[idx] = __float2bfloat16(v - __bfloat162float(h));
}

// ---------------- misc small kernels (unchanged from R1) ----------------
__device__ __forceinline__ float sigm(float x){ return 1.f/(1.f+expf(-x)); }
__device__ __forceinline__ float softplusf(float x){ return fmaxf(x,0.f)+log1pf(expf(-fabsf(x))); }

__global__ void k_zero(float* p, size_t n){
    size_t i = (size_t)blockIdx.x*blockDim.x + threadIdx.x;
    if (i < n) p[i] = 0.f;
}
__global__ void k_fill1(float* p, size_t n){
    size_t i = (size_t)blockIdx.x*blockDim.x + threadIdx.x;
    if (i < n) p[i] = 1.f;
}
__global__ void k_zero_int(int* p, int n){
    int i = blockIdx.x*blockDim.x + threadIdx.x;
    if (i < n) p[i] = 0;
}
__global__ void k_count(const int* __restrict__ lit){
    int e = blockIdx.x*blockDim.x + threadIdx.x;
    if (e < NE) atomicAdd(&g_deg[lit[e]], 1);
}
__global__ void k_weights(){
    int l = blockIdx.x*blockDim.x + threadIdx.x;
    if (l < NL) g_ws[O_DEGW + l] = rsqrtf(fmaxf((float)g_deg[l], 1.f));
    if (l < NV) g_ws[O_VDEGW + l] = 4.f*rsqrtf(fmaxf((float)(g_deg[l] + g_deg[l+NV]), 1.f));
}
__global__ void k_concat(const float* __restrict__ a, const float* __restrict__ nz,
                         float* __restrict__ x, int n){
    size_t i = (size_t)blockIdx.x*blockDim.x + threadIdx.x;
    if (i >= (size_t)n*132) return;
    int r = (int)(i/132), c = (int)(i%132);
    x[i] = (c < 128) ? a[(size_t)r*128 + c] : nz[(size_t)r*4 + (c-128)];
}
__global__ void k_csum(const int* __restrict__ lit, const int* __restrict__ cls){
    int e = blockIdx.x, f = threadIdx.x;
    int l = lit[e];
    float z = (l < NV) ? g_ws[O_VQ + (size_t)l*128 + f]
                       : -g_ws[O_VQ + (size_t)(l-NV)*128 + f];
    atomicAdd(&g_ws[O_CSUM + (size_t)cls[e]*128 + f], softplusf(z));
}
__global__ void k_scatter(const float* __restrict__ src, int sstride,
                          const int* __restrict__ gidx, const int* __restrict__ sidx,
                          float* __restrict__ dst){
    int e = blockIdx.x, f = threadIdx.x;
    atomicAdd(&dst[(size_t)sidx[e]*128 + f], src[(size_t)gidx[e]*sstride + f]);
}
__global__ void k_loss(){
    size_t i = (size_t)blockIdx.x*blockDim.x + threadIdx.x;
    if (i >= (size_t)NC*128) return;
    int c = (int)(i >> 7), f = (int)(i & 127);
    float s = sigm(g_ws[O_CQ + i]);
    float l = expf(-g_ws[O_CSUM + i]) * s;
    g_ws[O_LOSS + i] = l;
    size_t b = (size_t)c*384;
    g_ws[O_CMIN + b + f]       = g_ws[O_CLS + i];
    g_ws[O_CMIN + b + 128 + f] = 4.f * l;
    g_ws[O_CMIN + b + 256 + f] = l * (1.f - s) * INV_M;
}
__global__ void k_unit(){
    int v = blockIdx.x, f = threadIdx.x;
    size_t i = (size_t)v*128 + f;
    float vq = g_ws[O_VQ + i];
    float sp = sigm(vq);
    float sn = 1.f - sp;
    float g = -INV_M * (g_ws[O_DLITS + i]*sp - g_ws[O_DLITS + (size_t)NV*128 + i]*sn)
              * g_ws[O_VDEGW + v];
    size_t b = (size_t)v*512;
    g_ws[O_UNIT + b + f]        = g;
    g_ws[O_UNIT + b + 128 + f]  = g_ws[O_VARS + i];
    g_ws[O_UNIT + b + 256 + f]  = g_ws[O_VL + i] * g_ws[O_DEGW + v];
    g_ws[O_UNIT + b + 384 + f]  = g_ws[O_VL + (size_t)NV*128 + i] * g_ws[O_DEGW + NV + v];
}
__global__ void k_pn_stats(const float* __restrict__ x, int stride, int off, int n){
    int f = threadIdx.x;
    float s = 0.f, q = 0.f;
    for (int r = blockIdx.x; r < n; r += gridDim.x) {
        float v = x[(size_t)r*stride + off + f];
        s += v; q += v*v;
    }
    atomicAdd(&g_ws[O_STAT + f], s);
    atomicAdd(&g_ws[O_STAT + 128 + f], q);
}
__global__ void k_pn_scale(float n){
    int f = threadIdx.x;
    float mean = g_ws[O_STAT + f] / n;
    float var  = g_ws[O_STAT + 128 + f] / n - mean*mean;
    __shared__ float sh[128];
    sh[f] = var; __syncthreads();
    for (int s = 64; s > 0; s >>= 1) { if (f < s) sh[f] += sh[f+s]; __syncthreads(); }
    g_ws[O_STAT + f] = mean;
    if (f == 0) g_ws[O_STAT + 256] = rsqrtf(sh[0]*(1.f/128.f) + 1e-6f);
}
__global__ void k_pn_apply(const float* __restrict__ x, int stride, int off,
                           float* __restrict__ dst){
    int r = blockIdx.x, f = threadIdx.x;
    float scale = g_ws[O_STAT + 256];
    float v = (x[(size_t)r*stride + off + f] - g_ws[O_STAT + f]) * scale;
    size_t i = (size_t)r*128 + f;
    dst[i] = v*0.25f + 0.1f*dst[i];
}
__global__ void k_logits(const float* __restrict__ H, const float* __restrict__ w1,
                         const float* __restrict__ b1, float* __restrict__ out, int round){
    __shared__ float wv[128];
    int t = threadIdx.x;
    wv[t] = w1[t];
    __syncthreads();
    int warp = t >> 5, lane = t & 31;
    int row = blockIdx.x*4 + warp;
    float s = 0.f;
    #pragma unroll
    for (int i = lane; i < 128; i += 32) s += H[(size_t)row*128 + i] * wv[i];
    #pragma unroll
    for (int o = 16; o > 0; o >>= 1) s += __shfl_xor_sync(0xffffffffu, s, o);
    if (lane == 0) {
        float x = s + b1[0];
        out[(size_t)round*NC + row] = sigm(x);
        out[(size_t)4*NC + (size_t)round*NC + row] = softplusf(x);
    }
}

// ---------------- host ----------------
static constexpr int GEMM_SMEM = 81920;

static void mmgemm(const float* A, const __nv_bfloat16* Bh, const __nv_bfloat16* Bl,
                   const float* bias, float* C, int M, int K, int KP, int Ntot, int relu){
    dim3 grid(Ntot/128, M/128);
    k_mma<<<grid, 256, GEMM_SMEM>>>(A, Bh, Bl, bias, C, K, KP, Ntot, relu);
}

extern "C" void kernel_launch(void* const* d_in, const int* in_sizes, int n_in,
                              void* d_out, int out_size)
{
    (void)in_sizes; (void)n_in; (void)out_size;
    const int*   edge_lit    = (const int*)d_in[0];
    const int*   edge_clause = (const int*)d_in[1];
    const float* noise_v = (const float*)d_in[2];
    const float* noise_c = (const float*)d_in[3];
    const float* vq_w0 = (const float*)d_in[4];  const float* vq_b0 = (const float*)d_in[5];
    const float* vq_w1 = (const float*)d_in[6];  const float* vq_b1 = (const float*)d_in[7];
    const float* cq_w0 = (const float*)d_in[8];  const float* cq_b0 = (const float*)d_in[9];
    const float* cq_w1 = (const float*)d_in[10]; const float* cq_b1 = (const float*)d_in[11];
    const float* cm_w0 = (const float*)d_in[12]; const float* cm_b0 = (const float*)d_in[13];
    const float* cm_w1 = (const float*)d_in[14]; const float* cm_b1 = (const float*)d_in[15];
    const float* ug_w0 = (const float*)d_in[16]; const float* ug_b0 = (const float*)d_in[17];
    const float* ug_w1 = (const float*)d_in[18]; const float* ug_b1 = (const float*)d_in[19];
    const float* ug_w2 = (const float*)d_in[20]; const float* ug_b2 = (const float*)d_in[21];
    const float* co_w0 = (const float*)d_in[22]; const float* co_b0 = (const float*)d_in[23];
    const float* co_w1 = (const float*)d_in[24]; const float* co_b1 = (const float*)d_in[25];
    float* out = (float*)d_out;

    float* ws; cudaGetSymbolAddress((void**)&ws, g_ws);
    int* deg;  cudaGetSymbolAddress((void**)&deg, g_deg);
    __nv_bfloat16* wh = reinterpret_cast<__nv_bfloat16*>(ws + O_WT);
    __nv_bfloat16* wl = wh + WH_TOTAL;

    cudaFuncSetAttribute(k_mma, cudaFuncAttributeMaxDynamicSharedMemorySize, GEMM_SMEM);

    // ---- setup ----
    k_zero_int<<<(NL+255)/256, 256>>>(deg, NL);
    k_count<<<(NE+255)/256, 256>>>(edge_lit);
    k_weights<<<(NL+255)/256, 256>>>();
    {
        size_t n = (size_t)NV*128;
        k_fill1<<<(unsigned)((n+255)/256), 256>>>(ws + O_VARS, n);
        n = (size_t)NC*128;
        k_fill1<<<(unsigned)((n+255)/256), 256>>>(ws + O_CLS, n);
    }
    #define WSPLIT(src, off, K, N, KP) \
        k_wsplit<<<((N)*(KP)+255)/256, 256>>>(src, wh + (off), wl + (off), K, N, KP)
    WSPLIT(vq_w0, OW_vq0, 132, 128, 136);
    WSPLIT(vq_w1, OW_vq1, 128, 128, 128);
    WSPLIT(cq_w0, OW_cq0, 132, 128, 136);
    WSPLIT(cq_w1, OW_cq1, 128, 128, 128);
    WSPLIT(cm_w0, OW_cm0, 384, 256, 384);
    WSPLIT(cm_w1, OW_cm1, 256, 256, 256);
    WSPLIT(ug_w0, OW_ug0, 512, 256, 512);
    WSPLIT(ug_w1, OW_ug1, 256, 256, 256);
    WSPLIT(ug_w2, OW_ug2, 256, 128, 256);
    WSPLIT(co_w0, OW_co0, 128, 128, 128);
    #undef WSPLIT

    for (int r = 0; r < 4; r++) {
        const float* nv_r = noise_v + (size_t)r*NV*4;
        const float* nc_r = noise_c + (size_t)r*NC*4;

        k_concat<<<(unsigned)(((size_t)NV*132 + 255)/256), 256>>>(ws+O_VARS, nv_r, ws+O_XV, NV);
        k_concat<<<(unsigned)(((size_t)NC*132 + 255)/256), 256>>>(ws+O_CLS,  nc_r, ws+O_XC, NC);

        mmgemm(ws+O_XV, wh+OW_vq0, wl+OW_vq0, vq_b0, ws+O_HV, NV, 132, 136, 128, 1);
        mmgemm(ws+O_HV, wh+OW_vq1, wl+OW_vq1, vq_b1, ws+O_VQ, NV, 128, 128, 128, 0);
        mmgemm(ws+O_XC, wh+OW_cq0, wl+OW_cq0, cq_b0, ws+O_HC, NC, 132, 136, 128, 1);
        mmgemm(ws+O_HC, wh+OW_cq1, wl+OW_cq1, cq_b1, ws+O_CQ, NC, 128, 128, 128, 0);

        {
            size_t n = (size_t)NC*128;
            k_zero<<<(unsigned)((n+255)/256), 256>>>(ws+O_CSUM, n);
        }
        k_csum<<<NE, 128>>>(edge_lit, edge_clause);
        k_loss<<<(unsigned)(((size_t)NC*128 + 255)/256), 256>>>();
        {
            size_t n = (size_t)NL*128;
            k_zero<<<(unsigned)((n+255)/256), 256>>>(ws+O_DLITS, n);
        }
        k_scatter<<<NE, 128>>>(ws+O_LOSS, 128, edge_clause, edge_lit, ws+O_DLITS);

        mmgemm(ws+O_CMIN, wh+OW_cm0, wl+OW_cm0, cm_b0, ws+O_HC,    NC, 384, 384, 256, 1);
        mmgemm(ws+O_HC,   wh+OW_cm1, wl+OW_cm1, cm_b1, ws+O_CDATA, NC, 256, 256, 256, 0);

        {
            size_t n = (size_t)NL*128;
            k_zero<<<(unsigned)((n+255)/256), 256>>>(ws+O_VL, n);
        }
        k_scatter<<<NE, 128>>>(ws+O_CDATA, 256, edge_clause, edge_lit, ws+O_VL);

        k_zero<<<2, 256>>>(ws+O_STAT, 257);
        k_pn_stats<<<512, 128>>>(ws+O_CDATA, 256, 128, NC);
        k_pn_scale<<<1, 128>>>((float)NC);
        k_pn_apply<<<NC, 128>>>(ws+O_CDATA, 256, 128, ws+O_CLS);

        k_unit<<<NV, 128>>>();
        mmgemm(ws+O_UNIT, wh+OW_ug0, wl+OW_ug0, ug_b0, ws+O_HV,   NV, 512, 512, 256, 1);
        mmgemm(ws+O_HV,   wh+OW_ug1, wl+OW_ug1, ug_b1, ws+O_HV2,  NV, 256, 256, 256, 1);
        mmgemm(ws+O_HV2,  wh+OW_ug2, wl+OW_ug2, ug_b2, ws+O_VOUT, NV, 256, 256, 128, 0);

        k_zero<<<2, 256>>>(ws+O_STAT, 257);
        k_pn_stats<<<512, 128>>>(ws+O_VOUT, 128, 0, NV);
        k_pn_scale<<<1, 128>>>((float)NV);
        k_pn_apply<<<NV, 128>>>(ws+O_VOUT, 128, 0, ws+O_VARS);

        mmgemm(ws+O_CLS, wh+OW_co0, wl+OW_co0, co_b0, ws+O_HC, NC, 128, 128, 128, 1);
        k_logits<<<NC/4, 128>>>(ws+O_HC, co_w1, co_b1, out, r);
    }
}